// round 9
// baseline (speedup 1.0000x reference)
#include <cuda_runtime.h>
#include <cuda_bf16.h>
#include <cstdint>

// LayerNorm over last dim W=256 for (8,128,128,256) fp32 + per-channel affine.
// R8 base + 256-bit vector memory ops (sm_100+ PTX): each lane owns 8
// contiguous floats; ONE ld.global.nc.v8.f32 + ONE st.global.v8.f32 per
// thread covers the whole 1KB row per warp. Packed f32x2 warp reduce.

#define EPS 1e-8f
#define W_DIM 256
#define C_DIM 128

__global__ __launch_bounds__(256, 8)
void ln_v8_kernel(const float* __restrict__ inp,
                  const float* __restrict__ gain,
                  const float* __restrict__ bias,
                  float* __restrict__ out,
                  int n_rows)
{
    const int warp_in_block = threadIdx.x >> 5;
    const int lane = threadIdx.x & 31;
    const int row = blockIdx.x * 8 + warp_in_block;
    if (row >= n_rows) return;

    // Affine params (independent loads; overlap bulk-load latency).
    const int c = (row >> 7) & (C_DIM - 1);   // row = ((b*C+c)*H + h), H=128
    const float g = __ldg(gain + c);
    const float b = __ldg(bias + c);

    const float* pin  = inp + (size_t)row * W_DIM + lane * 8;
    float*       pout = out + (size_t)row * W_DIM + lane * 8;

    // Single 256-bit load: 8 contiguous floats per lane, 1024B per warp op.
    float x0, x1, x2, x3, x4, x5, x6, x7;
    asm volatile(
        "ld.global.nc.v8.f32 {%0, %1, %2, %3, %4, %5, %6, %7}, [%8];"
        : "=f"(x0), "=f"(x1), "=f"(x2), "=f"(x3),
          "=f"(x4), "=f"(x5), "=f"(x6), "=f"(x7)
        : "l"(pin));

    float s  = ((x0 + x1) + (x2 + x3)) + ((x4 + x5) + (x6 + x7));
    float ss = ((x0*x0 + x1*x1) + (x2*x2 + x3*x3))
             + ((x4*x4 + x5*x5) + (x6*x6 + x7*x7));

    // Packed (s,ss) warp reduce: 2 SHFL + 1 add.rn.f32x2 per level.
    uint64_t pair;
    asm("mov.b64 %0, {%1, %2};" : "=l"(pair) : "f"(s), "f"(ss));
    #pragma unroll
    for (int off = 16; off > 0; off >>= 1) {
        uint32_t lo, hi;
        asm("mov.b64 {%0, %1}, %2;" : "=r"(lo), "=r"(hi) : "l"(pair));
        lo = __shfl_xor_sync(0xFFFFFFFFu, lo, off);
        hi = __shfl_xor_sync(0xFFFFFFFFu, hi, off);
        uint64_t other;
        asm("mov.b64 %0, {%1, %2};" : "=l"(other) : "r"(lo), "r"(hi));
        asm("add.rn.f32x2 %0, %1, %2;" : "=l"(pair) : "l"(pair), "l"(other));
    }
    asm("mov.b64 {%0, %1}, %2;" : "=f"(s), "=f"(ss) : "l"(pair));

    const float inv_w = 1.0f / (float)W_DIM;
    float mean = s * inv_w;
    float var  = ss * inv_w - mean * mean;
    float rstd = rsqrtf(var + EPS);

    float scale = rstd * g;
    float shift = b - mean * scale;

    x0 = x0 * scale + shift;  x1 = x1 * scale + shift;
    x2 = x2 * scale + shift;  x3 = x3 * scale + shift;
    x4 = x4 * scale + shift;  x5 = x5 * scale + shift;
    x6 = x6 * scale + shift;  x7 = x7 * scale + shift;

    // Single 256-bit store.
    asm volatile(
        "st.global.v8.f32 [%0], {%1, %2, %3, %4, %5, %6, %7, %8};"
        :
        : "l"(pout),
          "f"(x0), "f"(x1), "f"(x2), "f"(x3),
          "f"(x4), "f"(x5), "f"(x6), "f"(x7)
        : "memory");
}

extern "C" void kernel_launch(void* const* d_in, const int* in_sizes, int n_in,
                              void* d_out, int out_size) {
    const float* inp  = (const float*)d_in[0];
    const float* gain = (const float*)d_in[1];
    const float* bias = (const float*)d_in[2];
    float* out = (float*)d_out;

    int n_rows = in_sizes[0] / W_DIM;   // 131072
    int blocks = (n_rows + 7) / 8;      // 16384, 8 warps (rows) per block

    ln_v8_kernel<<<blocks, 256>>>(inp, gain, bias, out, n_rows);
}

// round 10
// speedup vs baseline: 1.0007x; 1.0007x over previous
#include <cuda_runtime.h>
#include <cuda_bf16.h>
#include <cstdint>

// LayerNorm over last dim W=256 for (8,128,128,256) fp32 + per-channel affine.
// Half-warp per row: 16 lanes x 16 floats each. One warp = 2 adjacent rows.
// Shuffle reduction is only 4 levels (offsets 8,4,2,1 stay within each
// half-warp) and each level serves both rows in the same instructions.
// Loads/stores: 2x 256-bit vector ops per lane (contiguous 64B/lane).

#define EPS 1e-8f
#define W_DIM 256
#define C_DIM 128

__global__ __launch_bounds__(256, 8)
void ln_half_kernel(const float* __restrict__ inp,
                    const float* __restrict__ gain,
                    const float* __restrict__ bias,
                    float* __restrict__ out,
                    int n_pairs)
{
    const int warp_in_block = threadIdx.x >> 5;
    const int lane = threadIdx.x & 31;
    const int pair_idx = blockIdx.x * 8 + warp_in_block;
    if (pair_idx >= n_pairs) return;

    const int half = lane >> 4;        // 0 or 1: which row of the pair
    const int sub  = lane & 15;        // lane within half-warp
    const int row  = pair_idx * 2 + half;

    // Affine params (independent; overlap bulk-load latency).
    const int c = (row >> 7) & (C_DIM - 1);   // row = ((b*C+c)*H + h), H=128
    const float g = __ldg(gain + c);
    const float b = __ldg(bias + c);

    const float* pin  = inp + (size_t)row * W_DIM + sub * 16;
    float*       pout = out + (size_t)row * W_DIM + sub * 16;

    // Two 256-bit loads: 16 contiguous floats per lane.
    float x0,x1,x2,x3,x4,x5,x6,x7, y0,y1,y2,y3,y4,y5,y6,y7;
    asm volatile(
        "ld.global.nc.v8.f32 {%0, %1, %2, %3, %4, %5, %6, %7}, [%8];"
        : "=f"(x0), "=f"(x1), "=f"(x2), "=f"(x3),
          "=f"(x4), "=f"(x5), "=f"(x6), "=f"(x7)
        : "l"(pin));
    asm volatile(
        "ld.global.nc.v8.f32 {%0, %1, %2, %3, %4, %5, %6, %7}, [%8];"
        : "=f"(y0), "=f"(y1), "=f"(y2), "=f"(y3),
          "=f"(y4), "=f"(y5), "=f"(y6), "=f"(y7)
        : "l"(pin + 8));

    float s  = (((x0 + x1) + (x2 + x3)) + ((x4 + x5) + (x6 + x7)))
             + (((y0 + y1) + (y2 + y3)) + ((y4 + y5) + (y6 + y7)));
    float ss = (((x0*x0 + x1*x1) + (x2*x2 + x3*x3))
             +  ((x4*x4 + x5*x5) + (x6*x6 + x7*x7)))
             + (((y0*y0 + y1*y1) + (y2*y2 + y3*y3))
             +  ((y4*y4 + y5*y5) + (y6*y6 + y7*y7)));

    // Packed (s,ss) reduce over the half-warp: 4 levels, offsets 8,4,2,1.
    uint64_t pairv;
    asm("mov.b64 %0, {%1, %2};" : "=l"(pairv) : "f"(s), "f"(ss));
    #pragma unroll
    for (int off = 8; off > 0; off >>= 1) {
        uint32_t lo, hi;
        asm("mov.b64 {%0, %1}, %2;" : "=r"(lo), "=r"(hi) : "l"(pairv));
        lo = __shfl_xor_sync(0xFFFFFFFFu, lo, off);
        hi = __shfl_xor_sync(0xFFFFFFFFu, hi, off);
        uint64_t other;
        asm("mov.b64 %0, {%1, %2};" : "=l"(other) : "r"(lo), "r"(hi));
        asm("add.rn.f32x2 %0, %1, %2;" : "=l"(pairv) : "l"(pairv), "l"(other));
    }
    asm("mov.b64 {%0, %1}, %2;" : "=f"(s), "=f"(ss) : "l"(pairv));

    const float inv_w = 1.0f / (float)W_DIM;
    float mean = s * inv_w;
    float var  = ss * inv_w - mean * mean;
    float rstd = rsqrtf(var + EPS);

    float scale = rstd * g;
    float shift = b - mean * scale;

    x0 = x0*scale + shift;  x1 = x1*scale + shift;
    x2 = x2*scale + shift;  x3 = x3*scale + shift;
    x4 = x4*scale + shift;  x5 = x5*scale + shift;
    x6 = x6*scale + shift;  x7 = x7*scale + shift;
    y0 = y0*scale + shift;  y1 = y1*scale + shift;
    y2 = y2*scale + shift;  y3 = y3*scale + shift;
    y4 = y4*scale + shift;  y5 = y5*scale + shift;
    y6 = y6*scale + shift;  y7 = y7*scale + shift;

    asm volatile(
        "st.global.v8.f32 [%0], {%1, %2, %3, %4, %5, %6, %7, %8};"
        :
        : "l"(pout),
          "f"(x0), "f"(x1), "f"(x2), "f"(x3),
          "f"(x4), "f"(x5), "f"(x6), "f"(x7)
        : "memory");
    asm volatile(
        "st.global.v8.f32 [%0], {%1, %2, %3, %4, %5, %6, %7, %8};"
        :
        : "l"(pout + 8),
          "f"(y0), "f"(y1), "f"(y2), "f"(y3),
          "f"(y4), "f"(y5), "f"(y6), "f"(y7)
        : "memory");
}

extern "C" void kernel_launch(void* const* d_in, const int* in_sizes, int n_in,
                              void* d_out, int out_size) {
    const float* inp  = (const float*)d_in[0];
    const float* gain = (const float*)d_in[1];
    const float* bias = (const float*)d_in[2];
    float* out = (float*)d_out;

    int n_rows  = in_sizes[0] / W_DIM;   // 131072
    int n_pairs = n_rows / 2;            // 65536
    int blocks  = (n_pairs + 7) / 8;     // 8192, 8 warps (pairs) per block

    ln_half_kernel<<<blocks, 256>>>(inp, gain, bias, out, n_pairs);
}